// round 12
// baseline (speedup 1.0000x reference)
#include <cuda_runtime.h>
#include <cuda_bf16.h>
#include <cstring>

#define ZC 128
#define LDIM 16
#define KCODES 256
#define CDIM 8
#define NPOS 32768
#define WHPLANE 4096
#define RBLK 256           // positions per block (2 row-tiles of 128)

typedef unsigned long long u64;
typedef unsigned int u32;
typedef unsigned short u16;

#define S1f  2.0813689810056077f      // log2(e)^2
#define M2S1f (-4.1627379620112154f)  // -2*log2(e)^2

// Precomputed code tables (exact smem images), built once by prep_codes.
__device__ uint4  gBf[LDIM][KCODES / 8][32];   // GEMM1 B frags  256 KB
__device__ uint4  gB2[LDIM][KCODES / 16][32];  // GEMM2 B frags  128 KB
__device__ float4 gCN4[LDIM][KCODES / 16][4];  // permuted norms  16 KB

__device__ __forceinline__ float sqrt_ap(float x) {
    float r; asm("sqrt.approx.f32 %0, %1;" : "=f"(r) : "f"(x)); return r;
}
__device__ __forceinline__ float ex2_ap(float x) {
    float r; asm("ex2.approx.f32 %0, %1;" : "=f"(r) : "f"(x)); return r;
}
__device__ __forceinline__ u32 cat16(__nv_bfloat16 lo, __nv_bfloat16 hi) {
    u16 a, b; memcpy(&a, &lo, 2); memcpy(&b, &hi, 2);
    return (u32)a | ((u32)b << 16);
}
__device__ __forceinline__ u32 pkbf(float lo, float hi) {
    u32 r; asm("cvt.rn.bf16x2.f32 %0, %1, %2;" : "=r"(r) : "f"(hi), "f"(lo)); return r;
}
__device__ __forceinline__ void split3(float x, __nv_bfloat16& b0, __nv_bfloat16& b1, __nv_bfloat16& b2) {
    b0 = __float2bfloat16(x);
    float r = x - __bfloat162float(b0);
    b1 = __float2bfloat16(r);
    r = r - __bfloat162float(b1);
    b2 = __float2bfloat16(r);
}
__device__ __forceinline__ void hmma(float& d0, float& d1, float& d2, float& d3,
                                     u32 a0, u32 a1, u32 a2, u32 a3, u32 b0, u32 b1) {
    asm volatile(
        "mma.sync.aligned.m16n8k16.row.col.f32.bf16.bf16.f32 "
        "{%0,%1,%2,%3}, {%4,%5,%6,%7}, {%8,%9}, {%0,%1,%2,%3};"
        : "+f"(d0), "+f"(d1), "+f"(d2), "+f"(d3)
        : "r"(a0), "r"(a1), "r"(a2), "r"(a3), "r"(b0), "r"(b1));
}

// Tiny prep kernel: one block per latent, one thread per code. Builds the
// exact smem fragment images used by the main kernel.
__global__ void __launch_bounds__(256)
prep_codes(const float* __restrict__ codes) {
    const int l = blockIdx.x;
    const int k = threadIdx.x;
    const float4* cp = reinterpret_cast<const float4*>(codes) + ((size_t)l * KCODES + k) * 2;
    const float4 ca = cp[0];
    const float4 cb = cp[1];
    float c[8] = {ca.x, ca.y, ca.z, ca.w, cb.x, cb.y, cb.z, cb.w};
    u32 cs0[4], cs1[4], cs2[4];
    float cn = 0.f;
    #pragma unroll
    for (int i = 0; i < 4; i++) {
        __nv_bfloat16 x0, x1, x2, y0, y1, y2;
        split3(c[2*i],   x0, x1, x2);
        split3(c[2*i+1], y0, y1, y2);
        cs0[i] = cat16(x0, y0); cs1[i] = cat16(x1, y1); cs2[i] = cat16(x2, y2);
        cn = fmaf(c[2*i], c[2*i], cn);
        cn = fmaf(c[2*i+1], c[2*i+1], cn);
    }
    // permuted norm scatter
    const int nc = k >> 4, j = k & 15;
    reinterpret_cast<float*>(&gCN4[l][nc][(j >> 1) & 3])[(j & 1) + ((j >> 3) << 1)] = S1f * cn;
    // GEMM1 B fragments
    const int nc2 = k >> 3, cg = k & 7;
    #pragma unroll
    for (int qq = 0; qq < 4; qq++)
        gBf[l][nc2][cg * 4 + qq] = make_uint4(cs0[qq], cs1[qq], cs0[qq], cs2[qq]);
    // GEMM2 B fragments: 16-bit scatter
    const int t  = (j & 7) >> 1;
    const int e0 = ((j >> 3) << 1) + (j & 1);
    #pragma unroll
    for (int n = 0; n < 8; n++) {
        u16* us = reinterpret_cast<u16*>(&gB2[l][nc][n * 4 + t]);
        const int sh = (n & 1) * 16;
        us[e0]     = (u16)(cs0[n >> 1] >> sh);
        us[4 + e0] = (u16)(cs1[n >> 1] >> sh);
    }
}

// Main kernel: 256 threads, 8 warps, 256 positions (2 row-tiles) x one latent.
__global__ void __launch_bounds__(256)
sth_mma4(const float* __restrict__ z, const float* __restrict__ codes,
         float* __restrict__ out_soft, float* __restrict__ out_hard,
         float* __restrict__ out_idx)
{
    __shared__ uint4  sBf[KCODES / 8][32];   // 16 KB
    __shared__ uint4  sB2[KCODES / 16][32];  // 8 KB
    __shared__ u32    sA[RBLK][3][4];        // 12 KB
    __shared__ float4 sCN4[KCODES / 16][4];  // 1 KB
    __shared__ float  sHN[RBLK];             // 1 KB

    const int l    = blockIdx.y;
    const int tid  = threadIdx.x;
    const int lane = tid & 31;
    const int wid  = tid >> 5;

    // ---- preamble 1: vector-copy prepared code tables into smem ----
    {
        const uint4* s1 = &gBf[l][0][0];
        uint4* d1 = &sBf[0][0];
        #pragma unroll
        for (int i = 0; i < 4; i++) d1[tid + 256 * i] = s1[tid + 256 * i];
        const uint4* s2 = &gB2[l][0][0];
        uint4* d2 = &sB2[0][0];
        #pragma unroll
        for (int i = 0; i < 2; i++) d2[tid + 256 * i] = s2[tid + 256 * i];
        if (tid < 64) (&sCN4[0][0])[tid] = (&gCN4[l][0][0])[tid];
    }
    // ---- preamble 2: thread tid owns global row tid ----
    {
        const int pos = blockIdx.x * RBLK + tid;
        const int bb = pos >> 12, wh = pos & 4095;
        const float* zp = z + ((size_t)bb * ZC + (size_t)l * CDIM) * WHPLANE + wh;
        float h[8];
        float hn = 0.f;
        #pragma unroll
        for (int i = 0; i < 8; i++) { h[i] = zp[i * WHPLANE]; hn = fmaf(h[i], h[i], hn); }
        sHN[tid] = S1f * hn;
        #pragma unroll
        for (int i = 0; i < 4; i++) {
            __nv_bfloat16 x0, x1, x2, y0, y1, y2;
            split3(h[2*i],   x0, x1, x2);
            split3(h[2*i+1], y0, y1, y2);
            sA[tid][0][i] = cat16(x0, y0);
            sA[tid][1][i] = cat16(x1, y1);
            sA[tid][2][i] = cat16(x2, y2);
        }
    }
    __syncthreads();

    // ---- fragment context ----
    const int q  = lane & 3;
    const int br = wid * 16 + (lane >> 2);
    u32 Af[2][6];
    float hnr[2][2];
    #pragma unroll
    for (int rt = 0; rt < 2; rt++) {
        const int r0 = rt * 128 + br, r1 = r0 + 8;
        Af[rt][0] = sA[r0][0][q]; Af[rt][1] = sA[r1][0][q];
        Af[rt][2] = sA[r0][1][q]; Af[rt][3] = sA[r1][1][q];
        Af[rt][4] = sA[r0][2][q]; Af[rt][5] = sA[r1][2][q];
        hnr[rt][0] = sHN[r0];
        hnr[rt][1] = sHN[r1];
    }

    float sf[2][4] = {{0.f,0.f,0.f,0.f},{0.f,0.f,0.f,0.f}};
    float sume[2][2] = {{0.f,0.f},{0.f,0.f}};
    float mind[2][2] = {{3.4e38f,3.4e38f},{3.4e38f,3.4e38f}};
    // argmin index tracked as FLOAT holding (k - 2q): candidates are
    // nc*16 + {0,1,8,9} (exact small floats) -> FSETP/FSEL on fma pipe.
    float minkf[2][2] = {{0.f,0.f},{0.f,0.f}};
    float kbf = 0.f;   // (float)(nc*16)

    #pragma unroll 4
    for (int nc = 0; nc < KCODES / 16; nc++) {
        const uint4 B1a = sBf[2 * nc][lane];
        const uint4 B1b = sBf[2 * nc + 1][lane];
        const uint4 B2v = sB2[nc][lane];
        const float4 cn4 = sCN4[nc][q];
        const float kf0 = kbf, kf1 = kbf + 1.f, kf8 = kbf + 8.f, kf9 = kbf + 9.f;
        kbf += 16.f;

        #pragma unroll
        for (int rt = 0; rt < 2; rt++) {
            const u32 A00 = Af[rt][0], A10 = Af[rt][1];
            const u32 A01 = Af[rt][2], A11 = Af[rt][3];
            const u32 A02 = Af[rt][4], A12 = Af[rt][5];
            const float hn0 = hnr[rt][0], hn1 = hnr[rt][1];

            float g0 = 0.f, g1 = 0.f, g2 = 0.f, g3 = 0.f;
            hmma(g0, g1, g2, g3, A00, A10, A01, A11, B1a.x, B1a.y);
            hmma(g0, g1, g2, g3, A01, A11, A00, A10, B1a.x, B1a.y);
            hmma(g0, g1, g2, g3, A02, A12, A00, A10, B1a.z, B1a.w);
            float f0 = 0.f, f1 = 0.f, f2 = 0.f, f3 = 0.f;
            hmma(f0, f1, f2, f3, A00, A10, A01, A11, B1b.x, B1b.y);
            hmma(f0, f1, f2, f3, A01, A11, A00, A10, B1b.x, B1b.y);
            hmma(f0, f1, f2, f3, A02, A12, A00, A10, B1b.z, B1b.w);

            const float d00 = fmaf(g0, M2S1f, hn0 + cn4.x);
            const float d01 = fmaf(g1, M2S1f, hn0 + cn4.y);
            const float d10 = fmaf(g2, M2S1f, hn1 + cn4.x);
            const float d11 = fmaf(g3, M2S1f, hn1 + cn4.y);
            const float d08 = fmaf(f0, M2S1f, hn0 + cn4.z);
            const float d09 = fmaf(f1, M2S1f, hn0 + cn4.w);
            const float d18 = fmaf(f2, M2S1f, hn1 + cn4.z);
            const float d19 = fmaf(f3, M2S1f, hn1 + cn4.w);

            bool t;
            t = d00 < mind[rt][0]; mind[rt][0] = fminf(mind[rt][0], d00); minkf[rt][0] = t ? kf0 : minkf[rt][0];
            t = d01 < mind[rt][0]; mind[rt][0] = fminf(mind[rt][0], d01); minkf[rt][0] = t ? kf1 : minkf[rt][0];
            t = d08 < mind[rt][0]; mind[rt][0] = fminf(mind[rt][0], d08); minkf[rt][0] = t ? kf8 : minkf[rt][0];
            t = d09 < mind[rt][0]; mind[rt][0] = fminf(mind[rt][0], d09); minkf[rt][0] = t ? kf9 : minkf[rt][0];
            t = d10 < mind[rt][1]; mind[rt][1] = fminf(mind[rt][1], d10); minkf[rt][1] = t ? kf0 : minkf[rt][1];
            t = d11 < mind[rt][1]; mind[rt][1] = fminf(mind[rt][1], d11); minkf[rt][1] = t ? kf1 : minkf[rt][1];
            t = d18 < mind[rt][1]; mind[rt][1] = fminf(mind[rt][1], d18); minkf[rt][1] = t ? kf8 : minkf[rt][1];
            t = d19 < mind[rt][1]; mind[rt][1] = fminf(mind[rt][1], d19); minkf[rt][1] = t ? kf9 : minkf[rt][1];

            const float e00 = ex2_ap(0.0f - sqrt_ap(fabsf(d00)));
            const float e01 = ex2_ap(0.0f - sqrt_ap(fabsf(d01)));
            const float e10 = ex2_ap(0.0f - sqrt_ap(fabsf(d10)));
            const float e11 = ex2_ap(0.0f - sqrt_ap(fabsf(d11)));
            const float e08 = ex2_ap(0.0f - sqrt_ap(fabsf(d08)));
            const float e09 = ex2_ap(0.0f - sqrt_ap(fabsf(d09)));
            const float e18 = ex2_ap(0.0f - sqrt_ap(fabsf(d18)));
            const float e19 = ex2_ap(0.0f - sqrt_ap(fabsf(d19)));
            sume[rt][0] += (e00 + e01) + (e08 + e09);
            sume[rt][1] += (e10 + e11) + (e18 + e19);

            const u32 p0a0 = pkbf(e00, e01);
            const u32 p0a1 = pkbf(e10, e11);
            const u32 p0a2 = pkbf(e08, e09);
            const u32 p0a3 = pkbf(e18, e19);
            const u32 p1a0 = pkbf(e00 - __uint_as_float(p0a0 << 16), e01 - __uint_as_float(p0a0 & 0xFFFF0000u));
            const u32 p1a1 = pkbf(e10 - __uint_as_float(p0a1 << 16), e11 - __uint_as_float(p0a1 & 0xFFFF0000u));
            const u32 p1a2 = pkbf(e08 - __uint_as_float(p0a2 << 16), e09 - __uint_as_float(p0a2 & 0xFFFF0000u));
            const u32 p1a3 = pkbf(e18 - __uint_as_float(p0a3 << 16), e19 - __uint_as_float(p0a3 & 0xFFFF0000u));

            hmma(sf[rt][0], sf[rt][1], sf[rt][2], sf[rt][3], p0a0, p0a1, p0a2, p0a3, B2v.x, B2v.y);
            hmma(sf[rt][0], sf[rt][1], sf[rt][2], sf[rt][3], p1a0, p1a1, p1a2, p1a3, B2v.x, B2v.y);
            hmma(sf[rt][0], sf[rt][1], sf[rt][2], sf[rt][3], p0a0, p0a1, p0a2, p0a3, B2v.z, B2v.w);
        }
    }

    // ---- restore integer k (+2q) and merge across the 4 lanes per row ----
    int mink[2][2];
    #pragma unroll
    for (int rt = 0; rt < 2; rt++)
        #pragma unroll
        for (int rr = 0; rr < 2; rr++)
            mink[rt][rr] = (int)minkf[rt][rr] + 2 * q;

    #pragma unroll
    for (int rt = 0; rt < 2; rt++) {
        #pragma unroll
        for (int rr = 0; rr < 2; rr++) {
            #pragma unroll
            for (int m = 1; m <= 2; m <<= 1) {
                sume[rt][rr] += __shfl_xor_sync(0xffffffffu, sume[rt][rr], m);
                const float om = __shfl_xor_sync(0xffffffffu, mind[rt][rr], m);
                const int   ok = __shfl_xor_sync(0xffffffffu, mink[rt][rr], m);
                const bool  tt = (om < mind[rt][rr]) || (om == mind[rt][rr] && ok < mink[rt][rr]);
                mind[rt][rr] = tt ? om : mind[rt][rr];
                mink[rt][rr] = tt ? ok : mink[rt][rr];
            }
        }
    }

    // ---- outputs ----
    #pragma unroll
    for (int rt = 0; rt < 2; rt++) {
        const float inv0 = 1.0f / sume[rt][0];
        const float inv1 = 1.0f / sume[rt][1];
        const int pos0 = blockIdx.x * RBLK + rt * 128 + br;
        const int pos1 = pos0 + 8;
        float2* sp0 = reinterpret_cast<float2*>(out_soft + (size_t)pos0 * ZC + (size_t)l * CDIM + 2 * q);
        *sp0 = make_float2(sf[rt][0] * inv0, sf[rt][1] * inv0);
        float2* sp1 = reinterpret_cast<float2*>(out_soft + (size_t)pos1 * ZC + (size_t)l * CDIM + 2 * q);
        *sp1 = make_float2(sf[rt][2] * inv1, sf[rt][3] * inv1);
        if (q == 0) {
            if (out_hard) {
                const float4* cw0 = reinterpret_cast<const float4*>(codes) + ((size_t)l * KCODES + mink[rt][0]) * 2;
                const float4* cw1 = reinterpret_cast<const float4*>(codes) + ((size_t)l * KCODES + mink[rt][1]) * 2;
                float4* hp0 = reinterpret_cast<float4*>(out_hard + (size_t)pos0 * ZC + (size_t)l * CDIM);
                float4* hp1 = reinterpret_cast<float4*>(out_hard + (size_t)pos1 * ZC + (size_t)l * CDIM);
                hp0[0] = cw0[0]; hp0[1] = cw0[1];
                hp1[0] = cw1[0]; hp1[1] = cw1[1];
            }
            if (out_idx) {
                out_idx[(size_t)pos0 * LDIM + l] = (float)mink[rt][0];
                out_idx[(size_t)pos1 * LDIM + l] = (float)mink[rt][1];
            }
        }
    }
}

extern "C" void kernel_launch(void* const* d_in, const int* in_sizes, int n_in,
                              void* d_out, int out_size) {
    const float* z     = (const float*)d_in[0];
    const float* codes = (const float*)d_in[1];
    float* out = (float*)d_out;

    const long long softN = (long long)NPOS * ZC;
    const long long idxN  = (long long)NPOS * LDIM;
    float* soft = out;
    float* hard = ((long long)out_size >= 2 * softN) ? out + softN : nullptr;
    float* idxo = ((long long)out_size >= 2 * softN + idxN) ? out + 2 * softN : nullptr;

    prep_codes<<<LDIM, 256>>>(codes);
    dim3 grid(NPOS / RBLK, LDIM);
    sth_mma4<<<grid, 256>>>(z, codes, soft, hard, idxo);
}

// round 13
// speedup vs baseline: 1.0484x; 1.0484x over previous
#include <cuda_runtime.h>
#include <cuda_bf16.h>
#include <cstring>

#define ZC 128
#define LDIM 16
#define KCODES 256
#define CDIM 8
#define NPOS 32768
#define WHPLANE 4096
#define RBLK 256           // positions per block (2 row-tiles of 128)

typedef unsigned long long u64;
typedef unsigned int u32;
typedef unsigned short u16;

#define S1f  2.0813689810056077f      // log2(e)^2
#define M2S1f (-4.1627379620112154f)  // -2*log2(e)^2

// Precomputed code tables (exact smem images), built once by prep_codes.
__device__ uint4  gBf[LDIM][KCODES / 8][32];   // GEMM1 B frags  256 KB
__device__ uint4  gB2[LDIM][KCODES / 16][32];  // GEMM2 B frags  128 KB
__device__ float4 gCN4[LDIM][KCODES / 16][4];  // permuted norms  16 KB

__device__ __forceinline__ float sqrt_ap(float x) {
    float r; asm("sqrt.approx.f32 %0, %1;" : "=f"(r) : "f"(x)); return r;
}
__device__ __forceinline__ float ex2_ap(float x) {
    float r; asm("ex2.approx.f32 %0, %1;" : "=f"(r) : "f"(x)); return r;
}
__device__ __forceinline__ u32 cat16(__nv_bfloat16 lo, __nv_bfloat16 hi) {
    u16 a, b; memcpy(&a, &lo, 2); memcpy(&b, &hi, 2);
    return (u32)a | ((u32)b << 16);
}
__device__ __forceinline__ u32 pkbf(float lo, float hi) {
    u32 r; asm("cvt.rn.bf16x2.f32 %0, %1, %2;" : "=r"(r) : "f"(hi), "f"(lo)); return r;
}
__device__ __forceinline__ void split3(float x, __nv_bfloat16& b0, __nv_bfloat16& b1, __nv_bfloat16& b2) {
    b0 = __float2bfloat16(x);
    float r = x - __bfloat162float(b0);
    b1 = __float2bfloat16(r);
    r = r - __bfloat162float(b1);
    b2 = __float2bfloat16(r);
}
__device__ __forceinline__ void hmma(float& d0, float& d1, float& d2, float& d3,
                                     u32 a0, u32 a1, u32 a2, u32 a3, u32 b0, u32 b1) {
    asm volatile(
        "mma.sync.aligned.m16n8k16.row.col.f32.bf16.bf16.f32 "
        "{%0,%1,%2,%3}, {%4,%5,%6,%7}, {%8,%9}, {%0,%1,%2,%3};"
        : "+f"(d0), "+f"(d1), "+f"(d2), "+f"(d3)
        : "r"(a0), "r"(a1), "r"(a2), "r"(a3), "r"(b0), "r"(b1));
}

// Tiny prep kernel: one block per latent, one thread per code. Builds the
// exact smem fragment images used by the main kernel.
__global__ void __launch_bounds__(256)
prep_codes(const float* __restrict__ codes) {
    const int l = blockIdx.x;
    const int k = threadIdx.x;
    const float4* cp = reinterpret_cast<const float4*>(codes) + ((size_t)l * KCODES + k) * 2;
    const float4 ca = cp[0];
    const float4 cb = cp[1];
    float c[8] = {ca.x, ca.y, ca.z, ca.w, cb.x, cb.y, cb.z, cb.w};
    u32 cs0[4], cs1[4], cs2[4];
    float cn = 0.f;
    #pragma unroll
    for (int i = 0; i < 4; i++) {
        __nv_bfloat16 x0, x1, x2, y0, y1, y2;
        split3(c[2*i],   x0, x1, x2);
        split3(c[2*i+1], y0, y1, y2);
        cs0[i] = cat16(x0, y0); cs1[i] = cat16(x1, y1); cs2[i] = cat16(x2, y2);
        cn = fmaf(c[2*i], c[2*i], cn);
        cn = fmaf(c[2*i+1], c[2*i+1], cn);
    }
    // permuted norm scatter
    const int nc = k >> 4, j = k & 15;
    reinterpret_cast<float*>(&gCN4[l][nc][(j >> 1) & 3])[(j & 1) + ((j >> 3) << 1)] = S1f * cn;
    // GEMM1 B fragments
    const int nc2 = k >> 3, cg = k & 7;
    #pragma unroll
    for (int qq = 0; qq < 4; qq++)
        gBf[l][nc2][cg * 4 + qq] = make_uint4(cs0[qq], cs1[qq], cs0[qq], cs2[qq]);
    // GEMM2 B fragments: 16-bit scatter
    const int t  = (j & 7) >> 1;
    const int e0 = ((j >> 3) << 1) + (j & 1);
    #pragma unroll
    for (int n = 0; n < 8; n++) {
        u16* us = reinterpret_cast<u16*>(&gB2[l][nc][n * 4 + t]);
        const int sh = (n & 1) * 16;
        us[e0]     = (u16)(cs0[n >> 1] >> sh);
        us[4 + e0] = (u16)(cs1[n >> 1] >> sh);
    }
}

// Main kernel: 256 threads, 8 warps, 256 positions (2 row-tiles) x one latent.
// Mainloop identical to the 118.8us R11 version; preamble replaced with a
// vector copy of the prepared tables; occupancy pinned at 3 blocks/SM.
__global__ void __launch_bounds__(256, 3)
sth_mma5(const float* __restrict__ z, const float* __restrict__ codes,
         float* __restrict__ out_soft, float* __restrict__ out_hard,
         float* __restrict__ out_idx)
{
    __shared__ uint4  sBf[KCODES / 8][32];   // 16 KB
    __shared__ uint4  sB2[KCODES / 16][32];  // 8 KB
    __shared__ u32    sA[RBLK][3][4];        // 12 KB
    __shared__ float4 sCN4[KCODES / 16][4];  // 1 KB
    __shared__ float  sHN[RBLK];             // 1 KB

    const int l    = blockIdx.y;
    const int tid  = threadIdx.x;
    const int lane = tid & 31;
    const int wid  = tid >> 5;

    // ---- preamble 1: vector-copy prepared code tables into smem ----
    {
        const uint4* s1 = &gBf[l][0][0];
        uint4* d1 = &sBf[0][0];
        #pragma unroll
        for (int i = 0; i < 4; i++) d1[tid + 256 * i] = s1[tid + 256 * i];
        const uint4* s2 = &gB2[l][0][0];
        uint4* d2 = &sB2[0][0];
        #pragma unroll
        for (int i = 0; i < 2; i++) d2[tid + 256 * i] = s2[tid + 256 * i];
        if (tid < 64) (&sCN4[0][0])[tid] = (&gCN4[l][0][0])[tid];
    }
    // ---- preamble 2: thread tid owns global row tid ----
    {
        const int pos = blockIdx.x * RBLK + tid;
        const int bb = pos >> 12, wh = pos & 4095;
        const float* zp = z + ((size_t)bb * ZC + (size_t)l * CDIM) * WHPLANE + wh;
        float h[8];
        float hn = 0.f;
        #pragma unroll
        for (int i = 0; i < 8; i++) { h[i] = zp[i * WHPLANE]; hn = fmaf(h[i], h[i], hn); }
        sHN[tid] = S1f * hn;
        #pragma unroll
        for (int i = 0; i < 4; i++) {
            __nv_bfloat16 x0, x1, x2, y0, y1, y2;
            split3(h[2*i],   x0, x1, x2);
            split3(h[2*i+1], y0, y1, y2);
            sA[tid][0][i] = cat16(x0, y0);
            sA[tid][1][i] = cat16(x1, y1);
            sA[tid][2][i] = cat16(x2, y2);
        }
    }
    __syncthreads();

    // ---- fragment context: 2 row-tiles, rows r0/r1 per tile ----
    const int q  = lane & 3;
    const int br = wid * 16 + (lane >> 2);
    u32 Af[2][6];
    float hnr[2][2];
    #pragma unroll
    for (int rt = 0; rt < 2; rt++) {
        const int r0 = rt * 128 + br, r1 = r0 + 8;
        Af[rt][0] = sA[r0][0][q]; Af[rt][1] = sA[r1][0][q];
        Af[rt][2] = sA[r0][1][q]; Af[rt][3] = sA[r1][1][q];
        Af[rt][4] = sA[r0][2][q]; Af[rt][5] = sA[r1][2][q];
        hnr[rt][0] = sHN[r0];
        hnr[rt][1] = sHN[r1];
    }

    float sf[2][4] = {{0.f,0.f,0.f,0.f},{0.f,0.f,0.f,0.f}};
    float sume[2][2] = {{0.f,0.f},{0.f,0.f}};
    float mind[2][2] = {{3.4e38f,3.4e38f},{3.4e38f,3.4e38f}};
    int   mink[2][2] = {{0,0},{0,0}};

    for (int nc = 0; nc < KCODES / 16; nc++) {
        const uint4 B1a = sBf[2 * nc][lane];
        const uint4 B1b = sBf[2 * nc + 1][lane];
        const uint4 B2v = sB2[nc][lane];
        const float4 cn4 = sCN4[nc][q];
        const int kb = nc * 16 + 2 * q;

        #pragma unroll
        for (int rt = 0; rt < 2; rt++) {
            const u32 A00 = Af[rt][0], A10 = Af[rt][1];
            const u32 A01 = Af[rt][2], A11 = Af[rt][3];
            const u32 A02 = Af[rt][4], A12 = Af[rt][5];
            const float hn0 = hnr[rt][0], hn1 = hnr[rt][1];

            float g0 = 0.f, g1 = 0.f, g2 = 0.f, g3 = 0.f;
            hmma(g0, g1, g2, g3, A00, A10, A01, A11, B1a.x, B1a.y);
            hmma(g0, g1, g2, g3, A01, A11, A00, A10, B1a.x, B1a.y);
            hmma(g0, g1, g2, g3, A02, A12, A00, A10, B1a.z, B1a.w);
            float f0 = 0.f, f1 = 0.f, f2 = 0.f, f3 = 0.f;
            hmma(f0, f1, f2, f3, A00, A10, A01, A11, B1b.x, B1b.y);
            hmma(f0, f1, f2, f3, A01, A11, A00, A10, B1b.x, B1b.y);
            hmma(f0, f1, f2, f3, A02, A12, A00, A10, B1b.z, B1b.w);

            const float d00 = fmaf(g0, M2S1f, hn0 + cn4.x);
            const float d01 = fmaf(g1, M2S1f, hn0 + cn4.y);
            const float d10 = fmaf(g2, M2S1f, hn1 + cn4.x);
            const float d11 = fmaf(g3, M2S1f, hn1 + cn4.y);
            const float d08 = fmaf(f0, M2S1f, hn0 + cn4.z);
            const float d09 = fmaf(f1, M2S1f, hn0 + cn4.w);
            const float d18 = fmaf(f2, M2S1f, hn1 + cn4.z);
            const float d19 = fmaf(f3, M2S1f, hn1 + cn4.w);

            bool t;
            t = d00 < mind[rt][0]; mind[rt][0] = fminf(mind[rt][0], d00); mink[rt][0] = t ? kb     : mink[rt][0];
            t = d01 < mind[rt][0]; mind[rt][0] = fminf(mind[rt][0], d01); mink[rt][0] = t ? kb + 1 : mink[rt][0];
            t = d08 < mind[rt][0]; mind[rt][0] = fminf(mind[rt][0], d08); mink[rt][0] = t ? kb + 8 : mink[rt][0];
            t = d09 < mind[rt][0]; mind[rt][0] = fminf(mind[rt][0], d09); mink[rt][0] = t ? kb + 9 : mink[rt][0];
            t = d10 < mind[rt][1]; mind[rt][1] = fminf(mind[rt][1], d10); mink[rt][1] = t ? kb     : mink[rt][1];
            t = d11 < mind[rt][1]; mind[rt][1] = fminf(mind[rt][1], d11); mink[rt][1] = t ? kb + 1 : mink[rt][1];
            t = d18 < mind[rt][1]; mind[rt][1] = fminf(mind[rt][1], d18); mink[rt][1] = t ? kb + 8 : mink[rt][1];
            t = d19 < mind[rt][1]; mind[rt][1] = fminf(mind[rt][1], d19); mink[rt][1] = t ? kb + 9 : mink[rt][1];

            const float e00 = ex2_ap(0.0f - sqrt_ap(fabsf(d00)));
            const float e01 = ex2_ap(0.0f - sqrt_ap(fabsf(d01)));
            const float e10 = ex2_ap(0.0f - sqrt_ap(fabsf(d10)));
            const float e11 = ex2_ap(0.0f - sqrt_ap(fabsf(d11)));
            const float e08 = ex2_ap(0.0f - sqrt_ap(fabsf(d08)));
            const float e09 = ex2_ap(0.0f - sqrt_ap(fabsf(d09)));
            const float e18 = ex2_ap(0.0f - sqrt_ap(fabsf(d18)));
            const float e19 = ex2_ap(0.0f - sqrt_ap(fabsf(d19)));
            sume[rt][0] += (e00 + e01) + (e08 + e09);
            sume[rt][1] += (e10 + e11) + (e18 + e19);

            const u32 p0a0 = pkbf(e00, e01);
            const u32 p0a1 = pkbf(e10, e11);
            const u32 p0a2 = pkbf(e08, e09);
            const u32 p0a3 = pkbf(e18, e19);
            const u32 p1a0 = pkbf(e00 - __uint_as_float(p0a0 << 16), e01 - __uint_as_float(p0a0 & 0xFFFF0000u));
            const u32 p1a1 = pkbf(e10 - __uint_as_float(p0a1 << 16), e11 - __uint_as_float(p0a1 & 0xFFFF0000u));
            const u32 p1a2 = pkbf(e08 - __uint_as_float(p0a2 << 16), e09 - __uint_as_float(p0a2 & 0xFFFF0000u));
            const u32 p1a3 = pkbf(e18 - __uint_as_float(p0a3 << 16), e19 - __uint_as_float(p0a3 & 0xFFFF0000u));

            hmma(sf[rt][0], sf[rt][1], sf[rt][2], sf[rt][3], p0a0, p0a1, p0a2, p0a3, B2v.x, B2v.y);
            hmma(sf[rt][0], sf[rt][1], sf[rt][2], sf[rt][3], p1a0, p1a1, p1a2, p1a3, B2v.x, B2v.y);
            hmma(sf[rt][0], sf[rt][1], sf[rt][2], sf[rt][3], p0a0, p0a1, p0a2, p0a3, B2v.z, B2v.w);
        }
    }

    // ---- merge sume/argmin across the 4 lanes sharing each row ----
    #pragma unroll
    for (int rt = 0; rt < 2; rt++) {
        #pragma unroll
        for (int rr = 0; rr < 2; rr++) {
            #pragma unroll
            for (int m = 1; m <= 2; m <<= 1) {
                sume[rt][rr] += __shfl_xor_sync(0xffffffffu, sume[rt][rr], m);
                const float om = __shfl_xor_sync(0xffffffffu, mind[rt][rr], m);
                const int   ok = __shfl_xor_sync(0xffffffffu, mink[rt][rr], m);
                const bool  tt = (om < mind[rt][rr]) || (om == mind[rt][rr] && ok < mink[rt][rr]);
                mind[rt][rr] = tt ? om : mind[rt][rr];
                mink[rt][rr] = tt ? ok : mink[rt][rr];
            }
        }
    }

    // ---- outputs: 4 rows per lane-quad ----
    #pragma unroll
    for (int rt = 0; rt < 2; rt++) {
        const float inv0 = 1.0f / sume[rt][0];
        const float inv1 = 1.0f / sume[rt][1];
        const int pos0 = blockIdx.x * RBLK + rt * 128 + br;
        const int pos1 = pos0 + 8;
        float2* sp0 = reinterpret_cast<float2*>(out_soft + (size_t)pos0 * ZC + (size_t)l * CDIM + 2 * q);
        *sp0 = make_float2(sf[rt][0] * inv0, sf[rt][1] * inv0);
        float2* sp1 = reinterpret_cast<float2*>(out_soft + (size_t)pos1 * ZC + (size_t)l * CDIM + 2 * q);
        *sp1 = make_float2(sf[rt][2] * inv1, sf[rt][3] * inv1);
        if (q == 0) {
            if (out_hard) {
                const float4* cw0 = reinterpret_cast<const float4*>(codes) + ((size_t)l * KCODES + mink[rt][0]) * 2;
                const float4* cw1 = reinterpret_cast<const float4*>(codes) + ((size_t)l * KCODES + mink[rt][1]) * 2;
                float4* hp0 = reinterpret_cast<float4*>(out_hard + (size_t)pos0 * ZC + (size_t)l * CDIM);
                float4* hp1 = reinterpret_cast<float4*>(out_hard + (size_t)pos1 * ZC + (size_t)l * CDIM);
                hp0[0] = cw0[0]; hp0[1] = cw0[1];
                hp1[0] = cw1[0]; hp1[1] = cw1[1];
            }
            if (out_idx) {
                out_idx[(size_t)pos0 * LDIM + l] = (float)mink[rt][0];
                out_idx[(size_t)pos1 * LDIM + l] = (float)mink[rt][1];
            }
        }
    }
}

extern "C" void kernel_launch(void* const* d_in, const int* in_sizes, int n_in,
                              void* d_out, int out_size) {
    const float* z     = (const float*)d_in[0];
    const float* codes = (const float*)d_in[1];
    float* out = (float*)d_out;

    const long long softN = (long long)NPOS * ZC;
    const long long idxN  = (long long)NPOS * LDIM;
    float* soft = out;
    float* hard = ((long long)out_size >= 2 * softN) ? out + softN : nullptr;
    float* idxo = ((long long)out_size >= 2 * softN + idxN) ? out + 2 * softN : nullptr;

    prep_codes<<<LDIM, 256>>>(codes);
    dim3 grid(NPOS / RBLK, LDIM);
    sth_mma5<<<grid, 256>>>(z, codes, soft, hard, idxo);
}

// round 14
// speedup vs baseline: 1.0904x; 1.0400x over previous
#include <cuda_runtime.h>
#include <cuda_bf16.h>
#include <cstring>

#define ZC 128
#define LDIM 16
#define KCODES 256
#define CDIM 8
#define NPOS 32768
#define WHPLANE 4096
#define RBLK 256           // positions per block (2 row-tiles of 128)

typedef unsigned long long u64;
typedef unsigned int u32;
typedef unsigned short u16;

#define S1f  2.0813689810056077f      // log2(e)^2
#define M2S1f (-4.1627379620112154f)  // -2*log2(e)^2

__device__ __forceinline__ float sqrt_ap(float x) {
    float r; asm("sqrt.approx.f32 %0, %1;" : "=f"(r) : "f"(x)); return r;
}
__device__ __forceinline__ float ex2_ap(float x) {
    float r; asm("ex2.approx.f32 %0, %1;" : "=f"(r) : "f"(x)); return r;
}
__device__ __forceinline__ u32 cat16(__nv_bfloat16 lo, __nv_bfloat16 hi) {
    u16 a, b; memcpy(&a, &lo, 2); memcpy(&b, &hi, 2);
    return (u32)a | ((u32)b << 16);
}
__device__ __forceinline__ u32 pkbf(float lo, float hi) {
    u32 r; asm("cvt.rn.bf16x2.f32 %0, %1, %2;" : "=r"(r) : "f"(hi), "f"(lo)); return r;
}
__device__ __forceinline__ u64 pk2(float lo, float hi) {
    u64 r; asm("mov.b64 %0, {%1, %2};" : "=l"(r) : "f"(lo), "f"(hi)); return r;
}
__device__ __forceinline__ u64 fadd2(u64 a, u64 b) {
    u64 d; asm("add.rn.f32x2 %0, %1, %2;" : "=l"(d) : "l"(a), "l"(b)); return d;
}
// packed d2 assembly: (dlo,dhi) = (glo,ghi)*m2 + hc   [f32x2; movs are renames]
__device__ __forceinline__ void dassm(float& dlo, float& dhi, float glo, float ghi,
                                      u64 m2, u64 hc) {
    asm("{\n\t.reg .b64 a, d;\n\tmov.b64 a, {%2, %3};\n\t"
        "fma.rn.f32x2 d, a, %4, %5;\n\tmov.b64 {%0, %1}, d;\n\t}"
        : "=f"(dlo), "=f"(dhi) : "f"(glo), "f"(ghi), "l"(m2), "l"(hc));
}
__device__ __forceinline__ void split3(float x, __nv_bfloat16& b0, __nv_bfloat16& b1, __nv_bfloat16& b2) {
    b0 = __float2bfloat16(x);
    float r = x - __bfloat162float(b0);
    b1 = __float2bfloat16(r);
    r = r - __bfloat162float(b1);
    b2 = __float2bfloat16(r);
}
__device__ __forceinline__ void hmma(float& d0, float& d1, float& d2, float& d3,
                                     u32 a0, u32 a1, u32 a2, u32 a3, u32 b0, u32 b1) {
    asm volatile(
        "mma.sync.aligned.m16n8k16.row.col.f32.bf16.bf16.f32 "
        "{%0,%1,%2,%3}, {%4,%5,%6,%7}, {%8,%9}, {%0,%1,%2,%3};"
        : "+f"(d0), "+f"(d1), "+f"(d2), "+f"(d3)
        : "r"(a0), "r"(a1), "r"(a2), "r"(a3), "r"(b0), "r"(b1));
}

// Single kernel: 256 threads, 8 warps, 256 positions (2 row-tiles) x one latent.
// GEMM1 (exact split-bf16) -> dots; packed-f32x2 d2 assembly; f32 softmin
// epilogue; GEMM2 (P0C0+P1C0+P0C1) from in-register P fragments.
__global__ void __launch_bounds__(256, 3)
sth_mma6(const float* __restrict__ z, const float* __restrict__ codes,
         float* __restrict__ out_soft, float* __restrict__ out_hard,
         float* __restrict__ out_idx)
{
    __shared__ uint4      sBf[KCODES / 8][32];   // GEMM1 B frags 16 KB
    __shared__ uint4      sB2[KCODES / 16][32];  // GEMM2 B frags 8 KB
    __shared__ u32        sA[RBLK][3][4];        // A rows 12 KB
    __shared__ ulonglong2 sCN4[KCODES / 16][4];  // norm pairs (lo=(kb,kb+1), hi=(kb+8,kb+9)) 1 KB
    __shared__ float      sHN[RBLK];             // 1 KB

    const int l    = blockIdx.y;
    const int tid  = threadIdx.x;
    const int lane = tid & 31;
    const int wid  = tid >> 5;

    // ---- preamble 1: thread tid owns code k = tid ----
    {
        const float4* cp = reinterpret_cast<const float4*>(codes) + ((size_t)l * KCODES + tid) * 2;
        const float4 ca = cp[0];
        const float4 cb = cp[1];
        float c[8] = {ca.x, ca.y, ca.z, ca.w, cb.x, cb.y, cb.z, cb.w};
        u32 cs0[4], cs1[4], cs2[4];
        float cn = 0.f;
        #pragma unroll
        for (int i = 0; i < 4; i++) {
            __nv_bfloat16 x0, x1, x2, y0, y1, y2;
            split3(c[2*i],   x0, x1, x2);
            split3(c[2*i+1], y0, y1, y2);
            cs0[i] = cat16(x0, y0); cs1[i] = cat16(x1, y1); cs2[i] = cat16(x2, y2);
            cn = fmaf(c[2*i], c[2*i], cn);
            cn = fmaf(c[2*i+1], c[2*i+1], cn);
        }
        // permuted norm scatter: chunk nc, candidate slot q=(j>>1)&3, elem:
        // lo pair holds (kb, kb+1), hi pair holds (kb+8, kb+9)
        const int nc = tid >> 4, j = tid & 15;
        reinterpret_cast<float*>(&sCN4[nc][(j >> 1) & 3])[(j & 1) + ((j >> 3) << 1)] = S1f * cn;
        // GEMM1 B fragments
        const int nc2 = tid >> 3, cg = tid & 7;
        #pragma unroll
        for (int qq = 0; qq < 4; qq++)
            sBf[nc2][cg * 4 + qq] = make_uint4(cs0[qq], cs1[qq], cs0[qq], cs2[qq]);
        // GEMM2 B fragments: 16-bit scatter
        const int t  = (j & 7) >> 1;
        const int e0 = ((j >> 3) << 1) + (j & 1);
        #pragma unroll
        for (int n = 0; n < 8; n++) {
            u16* us = reinterpret_cast<u16*>(&sB2[nc][n * 4 + t]);
            const int sh = (n & 1) * 16;
            us[e0]     = (u16)(cs0[n >> 1] >> sh);
            us[4 + e0] = (u16)(cs1[n >> 1] >> sh);
        }
    }
    // ---- preamble 2: thread tid owns global row tid ----
    {
        const int pos = blockIdx.x * RBLK + tid;
        const int bb = pos >> 12, wh = pos & 4095;
        const float* zp = z + ((size_t)bb * ZC + (size_t)l * CDIM) * WHPLANE + wh;
        float h[8];
        float hn = 0.f;
        #pragma unroll
        for (int i = 0; i < 8; i++) { h[i] = zp[i * WHPLANE]; hn = fmaf(h[i], h[i], hn); }
        sHN[tid] = S1f * hn;
        #pragma unroll
        for (int i = 0; i < 4; i++) {
            __nv_bfloat16 x0, x1, x2, y0, y1, y2;
            split3(h[2*i],   x0, x1, x2);
            split3(h[2*i+1], y0, y1, y2);
            sA[tid][0][i] = cat16(x0, y0);
            sA[tid][1][i] = cat16(x1, y1);
            sA[tid][2][i] = cat16(x2, y2);
        }
    }
    __syncthreads();

    // ---- fragment context: 2 row-tiles, rows r0/r1 per tile ----
    const int q  = lane & 3;
    const int br = wid * 16 + (lane >> 2);
    u32 Af[2][6];
    u64 hnp[2][2];   // (hn,hn) pairs per rt per row
    #pragma unroll
    for (int rt = 0; rt < 2; rt++) {
        const int r0 = rt * 128 + br, r1 = r0 + 8;
        Af[rt][0] = sA[r0][0][q]; Af[rt][1] = sA[r1][0][q];
        Af[rt][2] = sA[r0][1][q]; Af[rt][3] = sA[r1][1][q];
        Af[rt][4] = sA[r0][2][q]; Af[rt][5] = sA[r1][2][q];
        hnp[rt][0] = pk2(sHN[r0], sHN[r0]);
        hnp[rt][1] = pk2(sHN[r1], sHN[r1]);
    }
    const u64 m2p = pk2(M2S1f, M2S1f);

    float sf[2][4] = {{0.f,0.f,0.f,0.f},{0.f,0.f,0.f,0.f}};
    float sume[2][2] = {{0.f,0.f},{0.f,0.f}};
    float mind[2][2] = {{3.4e38f,3.4e38f},{3.4e38f,3.4e38f}};
    int   mink[2][2] = {{0,0},{0,0}};

    for (int nc = 0; nc < KCODES / 16; nc++) {
        const uint4 B1a = sBf[2 * nc][lane];
        const uint4 B1b = sBf[2 * nc + 1][lane];
        const uint4 B2v = sB2[nc][lane];
        const ulonglong2 cnp = sCN4[nc][q];   // .x=(cn_kb,cn_kb1) .y=(cn_kb8,cn_kb9)
        const int kb = nc * 16 + 2 * q;

        #pragma unroll
        for (int rt = 0; rt < 2; rt++) {
            const u32 A00 = Af[rt][0], A10 = Af[rt][1];
            const u32 A01 = Af[rt][2], A11 = Af[rt][3];
            const u32 A02 = Af[rt][4], A12 = Af[rt][5];

            float g0 = 0.f, g1 = 0.f, g2 = 0.f, g3 = 0.f;
            hmma(g0, g1, g2, g3, A00, A10, A01, A11, B1a.x, B1a.y);
            hmma(g0, g1, g2, g3, A01, A11, A00, A10, B1a.x, B1a.y);
            hmma(g0, g1, g2, g3, A02, A12, A00, A10, B1a.z, B1a.w);
            float f0 = 0.f, f1 = 0.f, f2 = 0.f, f3 = 0.f;
            hmma(f0, f1, f2, f3, A00, A10, A01, A11, B1b.x, B1b.y);
            hmma(f0, f1, f2, f3, A01, A11, A00, A10, B1b.x, B1b.y);
            hmma(f0, f1, f2, f3, A02, A12, A00, A10, B1b.z, B1b.w);

            // packed d2 assembly: d = g*(-2 log2e^2) + (hn + cn), f32x2 lanes
            const u64 hc0lo = fadd2(cnp.x, hnp[rt][0]);
            const u64 hc0hi = fadd2(cnp.y, hnp[rt][0]);
            const u64 hc1lo = fadd2(cnp.x, hnp[rt][1]);
            const u64 hc1hi = fadd2(cnp.y, hnp[rt][1]);
            float d00, d01, d10, d11, d08, d09, d18, d19;
            dassm(d00, d01, g0, g1, m2p, hc0lo);
            dassm(d10, d11, g2, g3, m2p, hc1lo);
            dassm(d08, d09, f0, f1, m2p, hc0hi);
            dassm(d18, d19, f2, f3, m2p, hc1hi);

            bool t;
            t = d00 < mind[rt][0]; mind[rt][0] = fminf(mind[rt][0], d00); mink[rt][0] = t ? kb     : mink[rt][0];
            t = d01 < mind[rt][0]; mind[rt][0] = fminf(mind[rt][0], d01); mink[rt][0] = t ? kb + 1 : mink[rt][0];
            t = d08 < mind[rt][0]; mind[rt][0] = fminf(mind[rt][0], d08); mink[rt][0] = t ? kb + 8 : mink[rt][0];
            t = d09 < mind[rt][0]; mind[rt][0] = fminf(mind[rt][0], d09); mink[rt][0] = t ? kb + 9 : mink[rt][0];
            t = d10 < mind[rt][1]; mind[rt][1] = fminf(mind[rt][1], d10); mink[rt][1] = t ? kb     : mink[rt][1];
            t = d11 < mind[rt][1]; mind[rt][1] = fminf(mind[rt][1], d11); mink[rt][1] = t ? kb + 1 : mink[rt][1];
            t = d18 < mind[rt][1]; mind[rt][1] = fminf(mind[rt][1], d18); mink[rt][1] = t ? kb + 8 : mink[rt][1];
            t = d19 < mind[rt][1]; mind[rt][1] = fminf(mind[rt][1], d19); mink[rt][1] = t ? kb + 9 : mink[rt][1];

            const float e00 = ex2_ap(0.0f - sqrt_ap(fabsf(d00)));
            const float e01 = ex2_ap(0.0f - sqrt_ap(fabsf(d01)));
            const float e10 = ex2_ap(0.0f - sqrt_ap(fabsf(d10)));
            const float e11 = ex2_ap(0.0f - sqrt_ap(fabsf(d11)));
            const float e08 = ex2_ap(0.0f - sqrt_ap(fabsf(d08)));
            const float e09 = ex2_ap(0.0f - sqrt_ap(fabsf(d09)));
            const float e18 = ex2_ap(0.0f - sqrt_ap(fabsf(d18)));
            const float e19 = ex2_ap(0.0f - sqrt_ap(fabsf(d19)));
            sume[rt][0] += (e00 + e01) + (e08 + e09);
            sume[rt][1] += (e10 + e11) + (e18 + e19);

            const u32 p0a0 = pkbf(e00, e01);
            const u32 p0a1 = pkbf(e10, e11);
            const u32 p0a2 = pkbf(e08, e09);
            const u32 p0a3 = pkbf(e18, e19);
            const u32 p1a0 = pkbf(e00 - __uint_as_float(p0a0 << 16), e01 - __uint_as_float(p0a0 & 0xFFFF0000u));
            const u32 p1a1 = pkbf(e10 - __uint_as_float(p0a1 << 16), e11 - __uint_as_float(p0a1 & 0xFFFF0000u));
            const u32 p1a2 = pkbf(e08 - __uint_as_float(p0a2 << 16), e09 - __uint_as_float(p0a2 & 0xFFFF0000u));
            const u32 p1a3 = pkbf(e18 - __uint_as_float(p0a3 << 16), e19 - __uint_as_float(p0a3 & 0xFFFF0000u));

            hmma(sf[rt][0], sf[rt][1], sf[rt][2], sf[rt][3], p0a0, p0a1, p0a2, p0a3, B2v.x, B2v.y);
            hmma(sf[rt][0], sf[rt][1], sf[rt][2], sf[rt][3], p1a0, p1a1, p1a2, p1a3, B2v.x, B2v.y);
            hmma(sf[rt][0], sf[rt][1], sf[rt][2], sf[rt][3], p0a0, p0a1, p0a2, p0a3, B2v.z, B2v.w);
        }
    }

    // ---- merge sume/argmin across the 4 lanes sharing each row ----
    #pragma unroll
    for (int rt = 0; rt < 2; rt++) {
        #pragma unroll
        for (int rr = 0; rr < 2; rr++) {
            #pragma unroll
            for (int m = 1; m <= 2; m <<= 1) {
                sume[rt][rr] += __shfl_xor_sync(0xffffffffu, sume[rt][rr], m);
                const float om = __shfl_xor_sync(0xffffffffu, mind[rt][rr], m);
                const int   ok = __shfl_xor_sync(0xffffffffu, mink[rt][rr], m);
                const bool  tt = (om < mind[rt][rr]) || (om == mind[rt][rr] && ok < mink[rt][rr]);
                mind[rt][rr] = tt ? om : mind[rt][rr];
                mink[rt][rr] = tt ? ok : mink[rt][rr];
            }
        }
    }

    // ---- outputs: 4 rows per lane-quad ----
    #pragma unroll
    for (int rt = 0; rt < 2; rt++) {
        const float inv0 = 1.0f / sume[rt][0];
        const float inv1 = 1.0f / sume[rt][1];
        const int pos0 = blockIdx.x * RBLK + rt * 128 + br;
        const int pos1 = pos0 + 8;
        float2* sp0 = reinterpret_cast<float2*>(out_soft + (size_t)pos0 * ZC + (size_t)l * CDIM + 2 * q);
        *sp0 = make_float2(sf[rt][0] * inv0, sf[rt][1] * inv0);
        float2* sp1 = reinterpret_cast<float2*>(out_soft + (size_t)pos1 * ZC + (size_t)l * CDIM + 2 * q);
        *sp1 = make_float2(sf[rt][2] * inv1, sf[rt][3] * inv1);
        if (q == 0) {
            if (out_hard) {
                const float4* cw0 = reinterpret_cast<const float4*>(codes) + ((size_t)l * KCODES + mink[rt][0]) * 2;
                const float4* cw1 = reinterpret_cast<const float4*>(codes) + ((size_t)l * KCODES + mink[rt][1]) * 2;
                float4* hp0 = reinterpret_cast<float4*>(out_hard + (size_t)pos0 * ZC + (size_t)l * CDIM);
                float4* hp1 = reinterpret_cast<float4*>(out_hard + (size_t)pos1 * ZC + (size_t)l * CDIM);
                hp0[0] = cw0[0]; hp0[1] = cw0[1];
                hp1[0] = cw1[0]; hp1[1] = cw1[1];
            }
            if (out_idx) {
                out_idx[(size_t)pos0 * LDIM + l] = (float)mink[rt][0];
                out_idx[(size_t)pos1 * LDIM + l] = (float)mink[rt][1];
            }
        }
    }
}

extern "C" void kernel_launch(void* const* d_in, const int* in_sizes, int n_in,
                              void* d_out, int out_size) {
    const float* z     = (const float*)d_in[0];
    const float* codes = (const float*)d_in[1];
    float* out = (float*)d_out;

    const long long softN = (long long)NPOS * ZC;
    const long long idxN  = (long long)NPOS * LDIM;
    float* soft = out;
    float* hard = ((long long)out_size >= 2 * softN) ? out + softN : nullptr;
    float* idxo = ((long long)out_size >= 2 * softN + idxN) ? out + 2 * softN : nullptr;

    dim3 grid(NPOS / RBLK, LDIM);
    sth_mma6<<<grid, 256>>>(z, codes, soft, hard, idxo);
}